// round 1
// baseline (speedup 1.0000x reference)
#include <cuda_runtime.h>

// Chamfer distance loss on (2,8,4096,3) fp32 point clouds.
// loss = mean_b [ mean_i min_j d(p_i, t_j) + mean_j min_i d(p_i, t_j) ]
//      = (sum of all 2*16*4096 nearest-neighbor distances) / 65536
//
// Strategy: compute-bound brute force, d2 = x2s + (h_j - 2 x.y_j),
// with x2s hoisted out of the min. Inner loop uses packed fma.rn.f32x2
// (2 targets per instruction): 1.5 FMA-pipe instr + 1 FMNMX per pair.

#define NPTS   4096
#define THREADS 256
#define P       4                      // query points per thread
#define PREDS_PER_BLOCK (THREADS * P)  // 1024
#define CHUNK  2048                    // targets resident in SMEM per tile
#define NBATCH 16
#define NWARPS (THREADS / 32)

__device__ float g_sum;

__global__ void cd_zero_kernel() { g_sum = 0.0f; }

__global__ void cd_finalize_kernel(float* out) {
    out[0] = g_sum * (1.0f / (float)(NBATCH * NPTS));
}

__global__ void __launch_bounds__(THREADS)
cd_chamfer_kernel(const float* __restrict__ pred, const float* __restrict__ targ) {
    // grid: (NPTS/PREDS_PER_BLOCK, NBATCH, 2)
    const int batch = blockIdx.y;
    const int dir   = blockIdx.z;
    const float* __restrict__ A = dir ? targ : pred;  // query points
    const float* __restrict__ B = dir ? pred : targ;  // database points

    __shared__ __align__(16) float sy0[CHUNK];
    __shared__ __align__(16) float sy1[CHUNK];
    __shared__ __align__(16) float sy2[CHUNK];
    __shared__ __align__(16) float sh [CHUNK];
    __shared__ float swsum[NWARPS];

    const int tid = threadIdx.x;

    // ---- Load P query points; precompute packed (-2x) and ||x||^2 ----
    const int qbase = batch * NPTS + blockIdx.x * PREDS_PER_BLOCK;
    unsigned long long a0[P], a1[P], a2[P];
    float x2s[P], mlo[P], mhi[P];
#pragma unroll
    for (int p = 0; p < P; p++) {
        const int qi = qbase + p * THREADS + tid;
        const float x0 = A[qi * 3 + 0];
        const float x1 = A[qi * 3 + 1];
        const float x2 = A[qi * 3 + 2];
        x2s[p] = x0 * x0 + x1 * x1 + x2 * x2;
        const float m0 = -2.0f * x0, m1 = -2.0f * x1, m2 = -2.0f * x2;
        asm("mov.b64 %0, {%1, %1};" : "=l"(a0[p]) : "f"(m0));
        asm("mov.b64 %0, {%1, %1};" : "=l"(a1[p]) : "f"(m1));
        asm("mov.b64 %0, {%1, %1};" : "=l"(a2[p]) : "f"(m2));
        mlo[p] = 3.4e38f;
        mhi[p] = 3.4e38f;
    }

    // ---- Sweep all NPTS database points in CHUNK-sized SMEM tiles ----
    for (int c = 0; c < NPTS; c += CHUNK) {
        __syncthreads();   // previous tile fully consumed before overwrite
        const float* __restrict__ Bc = B + (size_t)(batch * NPTS + c) * 3;
        for (int i = tid; i < CHUNK; i += THREADS) {
            const float y0 = Bc[i * 3 + 0];
            const float y1 = Bc[i * 3 + 1];
            const float y2 = Bc[i * 3 + 2];
            sy0[i] = y0; sy1[i] = y1; sy2[i] = y2;
            sh[i]  = y0 * y0 + y1 * y1 + y2 * y2;
        }
        __syncthreads();

#pragma unroll 4
        for (int j = 0; j < CHUNK; j += 2) {
            // block-uniform broadcast LDS.64 loads (conflict-free)
            const unsigned long long y0p = *(const unsigned long long*)&sy0[j];
            const unsigned long long y1p = *(const unsigned long long*)&sy1[j];
            const unsigned long long y2p = *(const unsigned long long*)&sy2[j];
            const unsigned long long h2  = *(const unsigned long long*)&sh [j];
#pragma unroll
            for (int p = 0; p < P; p++) {
                unsigned long long t;
                asm("fma.rn.f32x2 %0, %1, %2, %3;" : "=l"(t) : "l"(a2[p]), "l"(y2p), "l"(h2));
                asm("fma.rn.f32x2 %0, %1, %2, %3;" : "=l"(t) : "l"(a1[p]), "l"(y1p), "l"(t));
                asm("fma.rn.f32x2 %0, %1, %2, %3;" : "=l"(t) : "l"(a0[p]), "l"(y0p), "l"(t));
                float tl, th;
                asm("mov.b64 {%0, %1}, %2;" : "=f"(tl), "=f"(th) : "l"(t));
                mlo[p] = fminf(mlo[p], tl);
                mhi[p] = fminf(mhi[p], th);
            }
        }
    }

    // ---- Per-thread: sqrt(clamped min d^2), sum over P points ----
    float lsum = 0.0f;
#pragma unroll
    for (int p = 0; p < P; p++) {
        float d2 = x2s[p] + fminf(mlo[p], mhi[p]);
        d2 = fmaxf(d2, 0.0f);
        lsum += sqrtf(d2);
    }

    // ---- Block reduction, one atomicAdd per block ----
#pragma unroll
    for (int off = 16; off > 0; off >>= 1)
        lsum += __shfl_down_sync(0xFFFFFFFFu, lsum, off);
    const int lane = tid & 31;
    const int wid  = tid >> 5;
    if (lane == 0) swsum[wid] = lsum;
    __syncthreads();
    if (wid == 0) {
        float v = (lane < NWARPS) ? swsum[lane] : 0.0f;
#pragma unroll
        for (int off = NWARPS / 2; off > 0; off >>= 1)
            v += __shfl_down_sync(0xFFFFFFFFu, v, off);
        if (lane == 0) atomicAdd(&g_sum, v);
    }
}

extern "C" void kernel_launch(void* const* d_in, const int* in_sizes, int n_in,
                              void* d_out, int out_size) {
    const float* pred = (const float*)d_in[0];
    const float* targ = (const float*)d_in[1];
    float* out = (float*)d_out;

    cd_zero_kernel<<<1, 1>>>();
    dim3 grid(NPTS / PREDS_PER_BLOCK, NBATCH, 2);
    cd_chamfer_kernel<<<grid, THREADS>>>(pred, targ);
    cd_finalize_kernel<<<1, 1>>>(out);
}

// round 2
// speedup vs baseline: 1.1189x; 1.1189x over previous
#include <cuda_runtime.h>

// Chamfer distance loss on (2,8,4096,3) fp32 point clouds.
// loss = (sum over both directions, all 16 batches, of nearest-neighbor
//         distances for each of 4096 points) / 65536
//
// Round-2 design: split target dim 8-ways for occupancy + balance,
// combine partial mins via atomicMin on int-bits of clamped d^2.

#define NPTS    4096
#define THREADS 256
#define P       4                       // query points per thread
#define QCHUNK  (THREADS * P)           // 1024 queries per block
#define TSPLIT  8
#define TCHUNK  (NPTS / TSPLIT)         // 512 targets per block
#define NBATCH  16
#define NQTOT   (2 * NBATCH * NPTS)     // 131072 query slots
#define FLT_MAX_BITS 0x7F7FFFFF

#define P2_BLOCKS 64
#define P2_THREADS 256

__device__ int   g_minbuf[NQTOT];
__device__ float g_sum;
__device__ unsigned int g_done;

// ---- init: minbuf = FLT_MAX bits, g_sum = 0, g_done = 0 ----
__global__ void __launch_bounds__(256) cd_init_kernel() {
    const int i = blockIdx.x * 256 + threadIdx.x;       // 128 blocks * 256 = 32768
    int4* p = reinterpret_cast<int4*>(g_minbuf);
    p[i] = make_int4(FLT_MAX_BITS, FLT_MAX_BITS, FLT_MAX_BITS, FLT_MAX_BITS);
    if (i == 0) { g_sum = 0.0f; g_done = 0u; }
}

// ---- pass 1: brute-force pairwise d^2, per-query min over target chunk ----
__global__ void __launch_bounds__(THREADS)
cd_pairs_kernel(const float* __restrict__ pred, const float* __restrict__ targ) {
    // grid: (QCHUNKS*TSPLIT = 4*8, NBATCH, 2)
    const int qx    = blockIdx.x >> 3;
    const int tx    = blockIdx.x & 7;
    const int batch = blockIdx.y;
    const int dir   = blockIdx.z;
    const float* __restrict__ A = dir ? targ : pred;  // query cloud
    const float* __restrict__ B = dir ? pred : targ;  // database cloud

    __shared__ __align__(16) float sy0[TCHUNK];
    __shared__ __align__(16) float sy1[TCHUNK];
    __shared__ __align__(16) float sy2[TCHUNK];
    __shared__ __align__(16) float sh [TCHUNK];

    const int tid = threadIdx.x;

    // fill target tile (SoA + precomputed ||y||^2)
    {
        const float* __restrict__ Bc = B + (size_t)(batch * NPTS + tx * TCHUNK) * 3;
        for (int i = tid; i < TCHUNK; i += THREADS) {
            const float y0 = Bc[i * 3 + 0];
            const float y1 = Bc[i * 3 + 1];
            const float y2 = Bc[i * 3 + 2];
            sy0[i] = y0; sy1[i] = y1; sy2[i] = y2;
            sh[i]  = y0 * y0 + y1 * y1 + y2 * y2;
        }
    }

    // load P query points; precompute packed (-2x) and ||x||^2
    const int qbase = batch * NPTS + qx * QCHUNK;
    unsigned long long a0[P], a1[P], a2[P];
    float x2s[P], mlo[P], mhi[P];
#pragma unroll
    for (int p = 0; p < P; p++) {
        const int qi = qbase + p * THREADS + tid;
        const float x0 = A[qi * 3 + 0];
        const float x1 = A[qi * 3 + 1];
        const float x2 = A[qi * 3 + 2];
        x2s[p] = x0 * x0 + x1 * x1 + x2 * x2;
        const float m0 = -2.0f * x0, m1 = -2.0f * x1, m2 = -2.0f * x2;
        asm("mov.b64 %0, {%1, %1};" : "=l"(a0[p]) : "f"(m0));
        asm("mov.b64 %0, {%1, %1};" : "=l"(a1[p]) : "f"(m1));
        asm("mov.b64 %0, {%1, %1};" : "=l"(a2[p]) : "f"(m2));
        mlo[p] = 3.4e38f;
        mhi[p] = 3.4e38f;
    }
    __syncthreads();

    // sweep the 512-target tile, 2 targets per packed fma
#pragma unroll 4
    for (int j = 0; j < TCHUNK; j += 2) {
        const unsigned long long y0p = *(const unsigned long long*)&sy0[j];
        const unsigned long long y1p = *(const unsigned long long*)&sy1[j];
        const unsigned long long y2p = *(const unsigned long long*)&sy2[j];
        const unsigned long long h2  = *(const unsigned long long*)&sh [j];
#pragma unroll
        for (int p = 0; p < P; p++) {
            unsigned long long t;
            asm("fma.rn.f32x2 %0, %1, %2, %3;" : "=l"(t) : "l"(a2[p]), "l"(y2p), "l"(h2));
            asm("fma.rn.f32x2 %0, %1, %2, %3;" : "=l"(t) : "l"(a1[p]), "l"(y1p), "l"(t));
            asm("fma.rn.f32x2 %0, %1, %2, %3;" : "=l"(t) : "l"(a0[p]), "l"(y0p), "l"(t));
            float tl, th;
            asm("mov.b64 {%0, %1}, %2;" : "=f"(tl), "=f"(th) : "l"(t));
            mlo[p] = fminf(mlo[p], tl);
            mhi[p] = fminf(mhi[p], th);
        }
    }

    // combine partial mins across target chunks (int-bit min, exact for d2>=0)
    const int obase = dir * (NBATCH * NPTS) + batch * NPTS + qx * QCHUNK;
#pragma unroll
    for (int p = 0; p < P; p++) {
        float d2 = x2s[p] + fminf(mlo[p], mhi[p]);
        d2 = fmaxf(d2, 0.0f);
        atomicMin(&g_minbuf[obase + p * THREADS + tid], __float_as_int(d2));
    }
}

// ---- pass 2: sqrt + global mean; last block writes output ----
__global__ void __launch_bounds__(P2_THREADS)
cd_reduce_kernel(float* __restrict__ out) {
    __shared__ float swsum[P2_THREADS / 32];
    const int tid = threadIdx.x;
    float lsum = 0.0f;
    for (int i = blockIdx.x * P2_THREADS + tid; i < NQTOT; i += P2_BLOCKS * P2_THREADS) {
        lsum += sqrtf(__int_as_float(g_minbuf[i]));
    }
#pragma unroll
    for (int off = 16; off > 0; off >>= 1)
        lsum += __shfl_down_sync(0xFFFFFFFFu, lsum, off);
    const int lane = tid & 31;
    const int wid  = tid >> 5;
    if (lane == 0) swsum[wid] = lsum;
    __syncthreads();
    if (wid == 0) {
        float v = (lane < P2_THREADS / 32) ? swsum[lane] : 0.0f;
#pragma unroll
        for (int off = (P2_THREADS / 32) / 2; off > 0; off >>= 1)
            v += __shfl_down_sync(0xFFFFFFFFu, v, off);
        if (lane == 0) {
            atomicAdd(&g_sum, v);
            __threadfence();
            const unsigned int r = atomicAdd(&g_done, 1u);
            if (r == P2_BLOCKS - 1) {
                const float total = atomicAdd(&g_sum, 0.0f);  // coherent L2 read
                out[0] = total * (1.0f / (float)(NBATCH * NPTS));
            }
        }
    }
}

extern "C" void kernel_launch(void* const* d_in, const int* in_sizes, int n_in,
                              void* d_out, int out_size) {
    const float* pred = (const float*)d_in[0];
    const float* targ = (const float*)d_in[1];
    float* out = (float*)d_out;

    cd_init_kernel<<<NQTOT / (256 * 4), 256>>>();
    dim3 grid((NPTS / QCHUNK) * TSPLIT, NBATCH, 2);
    cd_pairs_kernel<<<grid, THREADS>>>(pred, targ);
    cd_reduce_kernel<<<P2_BLOCKS, P2_THREADS>>>(out);
}

// round 3
// speedup vs baseline: 1.2918x; 1.1545x over previous
#include <cuda_runtime.h>

// Chamfer distance loss on (2,8,4096,3) fp32 point clouds.
// Round-3: SHARED distance matrix — each of the 16 batch matrices (4096x4096)
// is evaluated ONCE; every pair updates both the row-min (per prediction
// point) and the col-min (per target point). 268M pairs instead of 536M.
//
// Persistent kernel: 296 blocks (2/SM x 148) sweep 8192 flat chunks
// (batch, query-strip of 128, target-chunk of 256). Thread = 8 queries in
// registers x 16 targets from smem. Packed f32x2 FMA chain per 2 targets:
//   w = fma(m0,y0, fma(m1,y1, fma(m2,y2, x2+h)))   (m = -2x)
// Row mins accumulate in regs (flush per strip); col mins merge via smem
// atomicMin then one global atomicMin per target per chunk.

#define NPTS    4096
#define NBATCH  16
#define THREADS 256
#define TC      256                     // targets per chunk
#define QSTRIP  128                     // queries per strip
#define TCH     (NPTS / TC)             // 16 target chunks per batch
#define QSN     (NPTS / QSTRIP)         // 32 query strips per batch
#define NCHUNK  (NBATCH * QSN * TCH)    // 8192
#define GRID    296                     // 2 blocks/SM x 148 SMs
#define NQTOT   (2 * NBATCH * NPTS)     // 131072 min slots
#define FLT_MAX_BITS 0x7F7FFFFF
#define BIGF    3.4e38f

#define P2_BLOCKS 64
#define P2_THREADS 256

typedef unsigned long long ull;

__device__ int   g_minbuf[NQTOT];       // [0:65536)=row mins (pred side), [65536:)=col mins (targ side)
__device__ float g_sum;
__device__ unsigned int g_done;

__global__ void __launch_bounds__(256) cd_init_kernel() {
    const int i = blockIdx.x * 256 + threadIdx.x;   // 128 * 256 = 32768 int4s
    reinterpret_cast<int4*>(g_minbuf)[i] =
        make_int4(FLT_MAX_BITS, FLT_MAX_BITS, FLT_MAX_BITS, FLT_MAX_BITS);
    if (i == 0) { g_sum = 0.0f; g_done = 0u; }
}

__device__ __forceinline__ ull dupf(float v) {
    ull r;
    asm("mov.b64 %0, {%1, %1};" : "=l"(r) : "f"(v));
    return r;
}

__global__ void __launch_bounds__(THREADS, 2)
cd_main_kernel(const float* __restrict__ pred, const float* __restrict__ targ) {
    __shared__ __align__(16) float sy0[TC];
    __shared__ __align__(16) float sy1[TC];
    __shared__ __align__(16) float sy2[TC];
    __shared__ __align__(16) float sh [TC];
    __shared__ int scol[TC];

    const int tid = threadIdx.x;
    const int tx  = tid & 15;           // target group
    const int ty  = tid >> 4;           // query group

    const int c0 = (int)(((long long)blockIdx.x       * NCHUNK) / GRID);
    const int c1 = (int)(((long long)(blockIdx.x + 1) * NCHUNK) / GRID);

    ull  m0[8], m1[8], m2[8], x2d[8];
    float ralo[8], rahi[8], calo[8], cahi[8];
    int cur_strip = -1, cur_qbase = 0;

    scol[tid] = FLT_MAX_BITS;           // first syncthreads below publishes this

    for (int cid = c0; cid < c1; cid++) {
        const int b  = cid >> 9;        // 512 chunks per batch
        const int rr = cid & 511;
        const int qs = rr >> 4;
        const int tc = rr & 15;

        // ---- query strip management ----
        const int strip = (b << 5) | qs;
        if (strip != cur_strip) {
            if (cur_strip >= 0) {
#pragma unroll
                for (int i = 0; i < 8; i++) {
                    const float v = fminf(ralo[i], rahi[i]);
                    atomicMin(&g_minbuf[cur_qbase + (ty << 3) + i], __float_as_int(v));
                }
            }
            cur_strip = strip;
            cur_qbase = (b << 12) + (qs << 7);
            const float* __restrict__ qp = pred + (size_t)(cur_qbase + (ty << 3)) * 3;
#pragma unroll
            for (int i = 0; i < 8; i++) {
                const float x0 = qp[i * 3 + 0];
                const float x1 = qp[i * 3 + 1];
                const float x2 = qp[i * 3 + 2];
                m0[i]  = dupf(-2.0f * x0);
                m1[i]  = dupf(-2.0f * x1);
                m2[i]  = dupf(-2.0f * x2);
                x2d[i] = dupf(x0 * x0 + x1 * x1 + x2 * x2);
                ralo[i] = BIGF; rahi[i] = BIGF;
            }
        }

        // ---- fill target tile (one target per thread) ----
        {
            const float* __restrict__ bp = targ + (size_t)((b << 12) + (tc << 8) + tid) * 3;
            const float y0 = bp[0], y1 = bp[1], y2 = bp[2];
            sy0[tid] = y0; sy1[tid] = y1; sy2[tid] = y2;
            sh [tid] = y0 * y0 + y1 * y1 + y2 * y2;
        }
#pragma unroll
        for (int k = 0; k < 8; k++) { calo[k] = BIGF; cahi[k] = BIGF; }
        __syncthreads();    // A: tile + scol reset visible

        // ---- main: 8 target-pairs x 8 queries = 128 pairs/thread ----
#pragma unroll
        for (int k = 0; k < 8; k++) {
            const int w2 = (tx << 1) + (k << 5);       // word index (bank-conflict-free)
            const ull y0p = *(const ull*)(sy0 + w2);
            const ull y1p = *(const ull*)(sy1 + w2);
            const ull y2p = *(const ull*)(sy2 + w2);
            const ull hp  = *(const ull*)(sh  + w2);
#pragma unroll
            for (int q = 0; q < 8; q++) {
                ull s, w;
                asm("add.rn.f32x2 %0, %1, %2;"      : "=l"(s) : "l"(x2d[q]), "l"(hp));
                asm("fma.rn.f32x2 %0, %1, %2, %3;"  : "=l"(w) : "l"(m2[q]), "l"(y2p), "l"(s));
                asm("fma.rn.f32x2 %0, %1, %2, %3;"  : "=l"(w) : "l"(m1[q]), "l"(y1p), "l"(w));
                asm("fma.rn.f32x2 %0, %1, %2, %3;"  : "=l"(w) : "l"(m0[q]), "l"(y0p), "l"(w));
                float wl, wh;
                asm("mov.b64 {%0, %1}, %2;" : "=f"(wl), "=f"(wh) : "l"(w));
                ralo[q] = fminf(ralo[q], wl);
                rahi[q] = fminf(rahi[q], wh);
                calo[k] = fminf(calo[k], wl);
                cahi[k] = fminf(cahi[k], wh);
            }
        }

        // ---- merge col partials across the 16 ty groups (smem atomics) ----
#pragma unroll
        for (int k = 0; k < 8; k++) {
            const int w2 = (tx << 1) + (k << 5);
            atomicMin(&scol[w2],     __float_as_int(calo[k]));
            atomicMin(&scol[w2 + 1], __float_as_int(cahi[k]));
        }
        __syncthreads();    // B: scol complete; also protects tile before next fill

        // ---- one global atomicMin per target, then reset own slot ----
        atomicMin(&g_minbuf[(NBATCH * NPTS) + (b << 12) + (tc << 8) + tid], scol[tid]);
        scol[tid] = FLT_MAX_BITS;
    }

    // ---- final row flush ----
    if (cur_strip >= 0) {
#pragma unroll
        for (int i = 0; i < 8; i++) {
            const float v = fminf(ralo[i], rahi[i]);
            atomicMin(&g_minbuf[cur_qbase + (ty << 3) + i], __float_as_int(v));
        }
    }
}

// ---- pass 2: sqrt(clamp) + global mean; last block writes output ----
__global__ void __launch_bounds__(P2_THREADS)
cd_reduce_kernel(float* __restrict__ out) {
    __shared__ float swsum[P2_THREADS / 32];
    const int tid = threadIdx.x;
    float lsum = 0.0f;
    for (int i = blockIdx.x * P2_THREADS + tid; i < NQTOT; i += P2_BLOCKS * P2_THREADS) {
        lsum += sqrtf(fmaxf(__int_as_float(g_minbuf[i]), 0.0f));
    }
#pragma unroll
    for (int off = 16; off > 0; off >>= 1)
        lsum += __shfl_down_sync(0xFFFFFFFFu, lsum, off);
    const int lane = tid & 31;
    const int wid  = tid >> 5;
    if (lane == 0) swsum[wid] = lsum;
    __syncthreads();
    if (wid == 0) {
        float v = (lane < P2_THREADS / 32) ? swsum[lane] : 0.0f;
#pragma unroll
        for (int off = (P2_THREADS / 32) / 2; off > 0; off >>= 1)
            v += __shfl_down_sync(0xFFFFFFFFu, v, off);
        if (lane == 0) {
            atomicAdd(&g_sum, v);
            __threadfence();
            const unsigned int r = atomicAdd(&g_done, 1u);
            if (r == P2_BLOCKS - 1) {
                const float total = atomicAdd(&g_sum, 0.0f);
                out[0] = total * (1.0f / (float)(NBATCH * NPTS));
            }
        }
    }
}

extern "C" void kernel_launch(void* const* d_in, const int* in_sizes, int n_in,
                              void* d_out, int out_size) {
    const float* pred = (const float*)d_in[0];
    const float* targ = (const float*)d_in[1];
    float* out = (float*)d_out;

    cd_init_kernel<<<NQTOT / (256 * 4), 256>>>();
    cd_main_kernel<<<GRID, THREADS>>>(pred, targ);
    cd_reduce_kernel<<<P2_BLOCKS, P2_THREADS>>>(out);
}